// round 10
// baseline (speedup 1.0000x reference)
#include <cuda_runtime.h>
#include <cfloat>

// VQ nearest-codebook: z_e [32,64,64,64] f32 (B,C,H,W), embedding [1024,64] f32
// out = embedding[argmin_k ||z - e_k||^2] scattered back to [B,C,H,W].
//
// Pass 1: fp32x2 register-tiled GEMM, warp = 128 points x 8 codes
//         (z loads fully distinct, e loads warp-uniform broadcast -> LDS-light)
// Pass 2: exact fp64 re-rank of per-point top-2.

#define NPOINTS   131072
#define KCODES    1024
#define CDIM      64
#define MB        128         // points per block
#define NB        64          // codes per chunk
#define NCHUNK    (KCODES / NB)
#define NQ        16          // channel quads (4 channels each)

__device__ float g_eSq[KCODES];

__global__ void esq_kernel(const float* __restrict__ emb) {
    int k = blockIdx.x * 256 + threadIdx.x;
    if (k < KCODES) {
        const float* r = emb + k * CDIM;
        float s = 0.f;
        #pragma unroll
        for (int c = 0; c < CDIM; c++) s = fmaf(r[c], r[c], s);
        g_eSq[k] = s;
    }
}

__device__ __forceinline__ float2 u2f(unsigned long long u) {
    float2 f;
    asm("mov.b64 {%0,%1}, %2;" : "=f"(f.x), "=f"(f.y) : "l"(u));
    return f;
}

__global__ __launch_bounds__(256, 2) void vq_kernel(
    const float* __restrict__ z,
    const float* __restrict__ emb,
    float* __restrict__ out)
{
    // zsm4[q][p]: channels 4q..4q+3 of point p as 2x f32x2 (32768 B)
    __shared__ __align__(16) ulonglong2 zsm4[NQ * MB];
    // esm4[q][cs]: channels 4q..4q+3 of code (cs swizzled by +q) (16384 B)
    __shared__ __align__(16) ulonglong2 esm4[NQ * NB];
    __shared__ float esq_s[NB];
    __shared__ int bidx[MB];

    const int tid  = threadIdx.x;
    const int lane = tid & 31;
    const int w    = tid >> 5;      // warp id 0..7
    const int w8   = w * 8;         // this warp's code base within chunk

    const int n0  = blockIdx.x * MB;
    const int b   = n0 >> 12;       // H*W = 4096, 128 | 4096 so b constant
    const int hw0 = n0 & 4095;
    const float* zb = z + (size_t)b * CDIM * 4096 + hw0;

    // ---- stage z tile: [B?,C,H,W] -> channel-quad-packed smem ----
    {
        float* zsf = (float*)zsm4;
        #pragma unroll
        for (int i = 0; i < 32; i++) {
            int idx = i * 256 + tid;
            int ch = idx >> 7, p = idx & 127;              // gmem coalesced over p
            zsf[(ch >> 2) * 512 + p * 4 + (ch & 3)] = zb[ch * 4096 + p];
        }
    }

    float b1[4], b2[4];
    int   i1[4], i2[4];
    #pragma unroll
    for (int j = 0; j < 4; j++) {
        b1[j] = FLT_MAX; b2[j] = FLT_MAX; i1[j] = KCODES; i2[j] = KCODES;
    }

    unsigned long long acc[4][8];
    #pragma unroll
    for (int j = 0; j < 4; j++)
        #pragma unroll
        for (int k = 0; k < 8; k++) acc[j][k] = 0ULL;

    for (int cc = 0; cc < NCHUNK; cc++) {
        __syncthreads();   // esm safe to overwrite (covers zsm staging on cc==0)
        // ---- stage 64-code chunk, gmem-coalesced, +q swizzled columns ----
        {
            float* esf = (float*)esm4;
            const float* ebase = emb + cc * NB * CDIM;
            #pragma unroll
            for (int i = 0; i < 16; i++) {
                int idx = i * 256 + tid;
                int ch = idx & 63, c = idx >> 6;           // coalesced over ch
                int q = ch >> 2, r = ch & 3;
                int cs = (c + q) & 63;                     // conflict-free swizzle
                esf[q * 256 + cs * 4 + r] = ebase[c * CDIM + ch];
            }
            if (tid < NB) esq_s[tid] = g_eSq[cc * NB + tid];
        }
        __syncthreads();

        // ---- GEMM: warp covers 128 points x 8 codes, f32x2 packed ----
        #pragma unroll 2
        for (int q = 0; q < NQ; q++) {
            ulonglong2 zq[4];
            #pragma unroll
            for (int j = 0; j < 4; j++)
                zq[j] = zsm4[q * MB + lane + 32 * j];      // 32 distinct lanes
            #pragma unroll
            for (int h = 0; h < 2; h++) {
                ulonglong2 eq[4];
                #pragma unroll
                for (int k = 0; k < 4; k++)
                    eq[k] = esm4[q * NB + ((w8 + h * 4 + k + q) & 63)]; // broadcast
                #pragma unroll
                for (int j = 0; j < 4; j++)
                    #pragma unroll
                    for (int k = 0; k < 4; k++) {
                        asm("fma.rn.f32x2 %0, %1, %2, %0;"
                            : "+l"(acc[j][h * 4 + k]) : "l"(zq[j].x), "l"(eq[k].x));
                        asm("fma.rn.f32x2 %0, %1, %2, %0;"
                            : "+l"(acc[j][h * 4 + k]) : "l"(zq[j].y), "l"(eq[k].y));
                    }
            }
        }

        // ---- chunk epilogue: dist = ||e||^2 - 2*dot, running top-2 ----
        #pragma unroll
        for (int kk = 0; kk < 8; kk++) {
            int c = cc * NB + w8 + kk;
            float esq = esq_s[w8 + kk];
            #pragma unroll
            for (int j = 0; j < 4; j++) {
                float2 a = u2f(acc[j][kk]);
                acc[j][kk] = 0ULL;
                float dist = fmaf(-2.0f, a.x + a.y, esq);
                if (dist < b1[j]) {
                    b2[j] = b1[j]; i2[j] = i1[j];
                    b1[j] = dist;  i1[j] = c;
                } else if (dist < b2[j]) {
                    b2[j] = dist;  i2[j] = c;
                }
            }
        }
    }

    // ---- cross-warp top-2 merge (8 warps per point) ----
    __syncthreads();                       // all GEMM reads of zsm done
    float4* red = (float4*)zsm4;           // [point][warp] = (d1, i1, d2, i2)
    #pragma unroll
    for (int j = 0; j < 4; j++) {
        int p = lane + 32 * j;
        red[p * 8 + w] = make_float4(b1[j], __int_as_float(i1[j]),
                                     b2[j], __int_as_float(i2[j]));
    }
    __syncthreads();

    if (tid < MB) {
        float d1 = FLT_MAX, d2 = FLT_MAX;
        int   c1 = KCODES,  c2 = KCODES;
        #pragma unroll
        for (int t = 0; t < 8; t++) {
            float4 v = red[tid * 8 + t];
            float dv[2] = { v.x, v.z };
            int   iv[2] = { __float_as_int(v.y), __float_as_int(v.w) };
            #pragma unroll
            for (int u = 0; u < 2; u++) {
                float d = dv[u]; int i = iv[u];
                if (d < d1 || (d == d1 && i < c1)) {
                    d2 = d1; c2 = c1; d1 = d; c1 = i;
                } else if (d < d2 || (d == d2 && i < c2)) {
                    d2 = d; c2 = i;
                }
            }
        }
        // ---- exact fp64 re-rank of the two candidates ----
        int pick = c1;
        if (c2 < KCODES) {
            const float* e1 = emb + (size_t)c1 * CDIM;
            const float* e2 = emb + (size_t)c2 * CDIM;
            double s1 = 0.0, s2 = 0.0;
            #pragma unroll 8
            for (int ch = 0; ch < CDIM; ch++) {
                double zc = (double)zb[ch * 4096 + tid];   // coalesced over tid
                double q1 = zc - (double)e1[ch];
                double q2 = zc - (double)e2[ch];
                s1 = fma(q1, q1, s1);
                s2 = fma(q2, q2, s2);
            }
            if (s2 < s1 || (s2 == s1 && c2 < c1)) pick = c2;
        }
        bidx[tid] = pick;
    }
    __syncthreads();

    // ---- gather + scatter back to [B,C,H,W] (coalesced stores) ----
    #pragma unroll
    for (int i = 0; i < 32; i++) {
        int idx = i * 256 + tid;
        int ch = idx >> 7, p = idx & 127;
        out[(size_t)(b * CDIM + ch) * 4096 + hw0 + p] = emb[bidx[p] * CDIM + ch];
    }
}

extern "C" void kernel_launch(void* const* d_in, const int* in_sizes, int n_in,
                              void* d_out, int out_size) {
    const float* z   = (const float*)d_in[0];
    const float* emb = (const float*)d_in[1];
    float* out = (float*)d_out;
    esq_kernel<<<(KCODES + 255) / 256, 256>>>(emb);
    vq_kernel<<<NPOINTS / MB, 256>>>(z, emb, out);
}